// round 6
// baseline (speedup 1.0000x reference)
#include <cuda_runtime.h>
#include <cstdint>

// out[b, q, j] = float( max(0, q - 127) + j )   for B=8, Q=4096, K=64.
//
// Derivation: reference masks local window [q-127, q] to +inf, future to
// -inf, then stable top_k(64) -> always the 64 lowest window indices
// = max(0,q-127)+0..63. Input I is irrelevant. Output dtype fp32.
//
// R5 post-mortem: TMA (4.77us) == STG (4.74us) with all pipes idle ->
// fixed latency floor (launch + ramp), not throughput. Last lever: remove
// the thread0 serial TMA-issue tail. Warp w (of 8) issues batch w's 8KB
// bulk store with its own commit/wait -> 8 parallel TMA queues per CTA.

static constexpr int ROWS_PER_CTA = 32;                      // 4096 / 128
static constexpr int CHUNK_BYTES  = ROWS_PER_CTA * 64 * 4;   // 8192
static constexpr long long BATCH_BYTES = 4096LL * 64 * 4;    // 1 MB

__global__ void __launch_bounds__(256, 1)
TokenSelector_17755394801797_kernel(char* __restrict__ out) {
    __shared__ alignas(128) float tile[ROWS_PER_CTA * 64];

    int tid = threadIdx.x;
    int q0  = blockIdx.x * ROWS_PER_CTA;

    // Fill 32 rows x 64 floats = 512 float4; 2 per thread.
#pragma unroll
    for (int t = 0; t < 2; t++) {
        int f  = tid + t * 256;            // float4 index 0..511
        int r  = f >> 4;                   // row within chunk
        int j4 = (f & 15) << 2;            // column (multiple of 4)
        int q  = q0 + r;
        int start = q - 127;
        if (start < 0) start = 0;
        float b = (float)(start + j4);
        float4 v;
        v.x = b; v.y = b + 1.0f; v.z = b + 2.0f; v.w = b + 3.0f;
        reinterpret_cast<float4*>(tile)[f] = v;
    }
    __syncthreads();

    // Warp w stores the chunk to batch w. Lane 0 of each warp issues its
    // own bulk store + commit + wait -> 8 parallel TMA drains per CTA.
    int wid  = tid >> 5;
    int lane = tid & 31;
    if (lane == 0) {
        asm volatile("fence.proxy.async.shared::cta;" ::: "memory");
        uint32_t src;
        asm("{ .reg .u64 t; cvta.to.shared.u64 t, %1; cvt.u32.u64 %0, t; }"
            : "=r"(src) : "l"((const void*)tile));

        char* dst = out + (long long)wid * BATCH_BYTES
                        + (long long)blockIdx.x * CHUNK_BYTES;
        asm volatile(
            "cp.async.bulk.global.shared::cta.bulk_group [%0], [%1], %2;"
            :: "l"(dst), "r"(src), "n"(CHUNK_BYTES) : "memory");
        asm volatile("cp.async.bulk.commit_group;" ::: "memory");
        asm volatile("cp.async.bulk.wait_group.read 0;" ::: "memory");
    }
}

extern "C" void kernel_launch(void* const* d_in, const int* in_sizes, int n_in,
                              void* d_out, int out_size) {
    (void)d_in; (void)in_sizes; (void)n_in; (void)out_size;
    TokenSelector_17755394801797_kernel<<<128, 256>>>((char*)d_out);
}